// round 16
// baseline (speedup 1.0000x reference)
#include <cuda_runtime.h>
#include <cuda_fp16.h>
#include <stdint.h>

#define DIMV 128
#define NTOK (2*32*8192)
#define NELEM_LL (524288LL * 128LL)
#define NTHREADS 1024
#define NTILES 4096
#define GRID 152
#define PITCH 136
#define ROWB (PITCH * 2)             // 272
#define TILE_B (128 * ROWB)          // 34816

// smem byte offsets
#define SM_P1   0
#define SM_P2   34816
#define SM_PT1  69632
#define SM_R1   104448
#define SM_R2   139264
#define SM_SGN  174080
#define SM_IDX  208896               // 2 buffers x 4096 B
#define SM_NORM 217088               // 2 buffers x 512 B
#define SM_TOTAL 218112

typedef unsigned long long u64t;

__device__ __align__(16) __half gP1[128 * PITCH];
__device__ __align__(16) __half gP2[128 * PITCH];
__device__ __align__(16) __half gPT1[128 * PITCH];

__device__ __forceinline__ uint32_t hpack(__half a, __half b){
    __half2 t = __halves2half2(a, b);
    return *reinterpret_cast<uint32_t*>(&t);
}
__device__ __forceinline__ uint32_t su(const void* p){
    uint32_t a;
    asm("{ .reg .u64 t; cvta.to.shared.u64 t, %1; cvt.u32.u64 %0, t; }" : "=r"(a) : "l"(p));
    return a;
}

__global__ void prep_kernel(const float* __restrict__ proj){
    int i = blockIdx.x * blockDim.x + threadIdx.x;
    int e = i >> 7, d = i & 127;
    float v = proj[i];
    __half h1 = __float2half_rn(v);
    __half h2 = __float2half_rn(v - __half2float(h1));
    gP1[e * PITCH + d] = h1;
    gP2[e * PITCH + d] = h2;
    gPT1[d * PITCH + e] = h1;
}

extern __shared__ char smc[];

#define LDSM4(r0_, r1_, r2_, r3_, addr_) \
    asm volatile("ldmatrix.sync.aligned.m8n8.x4.shared.b16 {%0,%1,%2,%3}, [%4];" \
        : "=r"(r0_), "=r"(r1_), "=r"(r2_), "=r"(r3_) : "r"(addr_))

#define MMA16816(acc_, a_, b0_, b1_) \
    asm volatile("mma.sync.aligned.m16n8k16.row.col.f32.f16.f16.f32 " \
        "{%0,%1,%2,%3}, {%4,%5,%6,%7}, {%8,%9}, {%0,%1,%2,%3};" \
        : "+f"((acc_)[0]), "+f"((acc_)[1]), "+f"((acc_)[2]), "+f"((acc_)[3]) \
        : "r"((a_)[0]), "r"((a_)[1]), "r"((a_)[2]), "r"((a_)[3]), "r"(b0_), "r"(b1_))

// quad barrier: 4 warps (128 threads) sharing one mrow group
#define QBAR(id_) asm volatile("bar.sync %0, 128;" :: "r"(id_) : "memory")

// GEMM1 only (prologue): acc1 += r1*P1 + r2*P1 + r1*P2   (warp tile 16x32)
__device__ __forceinline__ void gemm1_only(float acc[4][4],
                                           uint32_t aR1, uint32_t aR2,
                                           uint32_t bP1, uint32_t bP2){
    #pragma unroll
    for (int kt = 0; kt < 8; kt++){
        uint32_t A1[4], A2[4];
        LDSM4(A1[0], A1[1], A1[2], A1[3], aR1 + kt * 32);
        LDSM4(A2[0], A2[1], A2[2], A2[3], aR2 + kt * 32);
        {
            uint32_t B[4][2];
            #pragma unroll
            for (int np = 0; np < 2; np++)
                LDSM4(B[2*np][0], B[2*np][1], B[2*np+1][0], B[2*np+1][1], bP1 + np * (16 * ROWB) + kt * 32);
            #pragma unroll
            for (int nt = 0; nt < 4; nt++){
                MMA16816(acc[nt], A1, B[nt][0], B[nt][1]);
                MMA16816(acc[nt], A2, B[nt][0], B[nt][1]);
            }
        }
        {
            uint32_t B[4][2];
            #pragma unroll
            for (int np = 0; np < 2; np++)
                LDSM4(B[2*np][0], B[2*np][1], B[2*np+1][0], B[2*np+1][1], bP2 + np * (16 * ROWB) + kt * 32);
            #pragma unroll
            for (int nt = 0; nt < 4; nt++)
                MMA16816(acc[nt], A1, B[nt][0], B[nt][1]);
        }
    }
}

// fused: acc1 = GEMM1(next tile), acc2 = GEMM2(cur tile, signs * PT1)
__device__ __forceinline__ void gemms_fused(float acc1[4][4], float acc2[4][4],
                                            uint32_t aR1, uint32_t aR2,
                                            uint32_t bP1, uint32_t bP2,
                                            uint32_t aSG, uint32_t bPT){
    #pragma unroll
    for (int kt = 0; kt < 8; kt++){
        uint32_t A1[4], A2[4];
        LDSM4(A1[0], A1[1], A1[2], A1[3], aR1 + kt * 32);
        LDSM4(A2[0], A2[1], A2[2], A2[3], aR2 + kt * 32);
        {
            uint32_t B[4][2];
            #pragma unroll
            for (int np = 0; np < 2; np++)
                LDSM4(B[2*np][0], B[2*np][1], B[2*np+1][0], B[2*np+1][1], bP1 + np * (16 * ROWB) + kt * 32);
            #pragma unroll
            for (int nt = 0; nt < 4; nt++){
                MMA16816(acc1[nt], A1, B[nt][0], B[nt][1]);
                MMA16816(acc1[nt], A2, B[nt][0], B[nt][1]);
            }
        }
        {
            uint32_t B[4][2];
            #pragma unroll
            for (int np = 0; np < 2; np++)
                LDSM4(B[2*np][0], B[2*np][1], B[2*np+1][0], B[2*np+1][1], bP2 + np * (16 * ROWB) + kt * 32);
            #pragma unroll
            for (int nt = 0; nt < 4; nt++)
                MMA16816(acc1[nt], A1, B[nt][0], B[nt][1]);
        }
        {
            uint32_t S[4], T[4][2];
            LDSM4(S[0], S[1], S[2], S[3], aSG + kt * 32);
            #pragma unroll
            for (int np = 0; np < 2; np++)
                LDSM4(T[2*np][0], T[2*np][1], T[2*np+1][0], T[2*np+1][1], bPT + np * (16 * ROWB) + kt * 32);
            #pragma unroll
            for (int nt = 0; nt < 4; nt++)
                MMA16816(acc2[nt], S, T[nt][0], T[nt][1]);
        }
    }
}

// GEMM2 only (final tile)
__device__ __forceinline__ void gemm2_only(float acc[4][4], uint32_t aSG, uint32_t bPT){
    #pragma unroll
    for (int kt = 0; kt < 8; kt++){
        uint32_t S[4], T[4][2];
        LDSM4(S[0], S[1], S[2], S[3], aSG + kt * 32);
        #pragma unroll
        for (int np = 0; np < 2; np++)
            LDSM4(T[2*np][0], T[2*np][1], T[2*np+1][0], T[2*np+1][1], bPT + np * (16 * ROWB) + kt * 32);
        #pragma unroll
        for (int nt = 0; nt < 4; nt++)
            MMA16816(acc[nt], S, T[nt][0], T[nt][1]);
    }
}

// phaseA, quad-local mapping: quad q handles tokens [16q, 16q+16).
__device__ __forceinline__ void phaseA(int tile, int p, const float* __restrict__ x,
                                       float* __restrict__ o_idx, float* __restrict__ o_norm,
                                       float c0, float c1, float c2, float c3,
                                       float b0, float b1, float b2, int tid){
    const int tok = ((tid >> 7) << 4) + ((tid & 127) >> 3);
    const int q = tid & 7;
    const int tok0 = tile * 128;
    const float* xr = x + (size_t)(tok0 + tok) * DIMV + q * 16;
    char* r1t = smc + SM_R1 + (tok * PITCH + q * 16) * 2;
    char* r2t = smc + SM_R2 + (tok * PITCH + q * 16) * 2;
    unsigned char* idxb = (unsigned char*)(smc + SM_IDX + p * 4096);
    float* norms = (float*)(smc + SM_NORM + p * 512);

    float ssq = 0.0f;
    uint32_t packed = 0;
    #pragma unroll
    for (int j = 0; j < 4; j++){
        float4 xv = ((const float4*)xr)[j];
        float vf[4] = {xv.x, xv.y, xv.z, xv.w};
        __half h1[4], h2[4];
        float iv[4];
        #pragma unroll
        for (int qq = 0; qq < 4; qq++){
            float v = vf[qq];
            int ix = (v > b0) + (v > b1) + (v > b2);
            float m = (ix == 0) ? c0 : (ix == 1) ? c1 : (ix == 2) ? c2 : c3;
            float r = v - m;
            ssq += r * r;
            iv[qq] = (float)ix;
            packed |= ((uint32_t)ix) << ((j * 4 + qq) * 2);
            h1[qq] = __float2half_rn(r);
            h2[qq] = __float2half_rn(r - __half2float(h1[qq]));
        }
        uint2 w1, w2;
        w1.x = hpack(h1[0], h1[1]); w1.y = hpack(h1[2], h1[3]);
        w2.x = hpack(h2[0], h2[1]); w2.y = hpack(h2[2], h2[3]);
        *(uint2*)(r1t + j * 8) = w1;
        *(uint2*)(r2t + j * 8) = w2;
        if (o_idx)
            *(float4*)(o_idx + (size_t)(tok0 + tok) * DIMV + q * 16 + 4 * j) =
                make_float4(iv[0], iv[1], iv[2], iv[3]);
    }
    *(uint32_t*)(idxb + tok * 32 + q * 4) = packed;
    ssq += __shfl_xor_sync(0xffffffffu, ssq, 1);
    ssq += __shfl_xor_sync(0xffffffffu, ssq, 2);
    ssq += __shfl_xor_sync(0xffffffffu, ssq, 4);
    if (q == 0){
        float nv = sqrtf(ssq);
        norms[tok] = nv;
        if (o_norm) o_norm[tok0 + tok] = nv;
    }
}

__global__ void __launch_bounds__(NTHREADS, 1)
turboquant_mma_kernel(const float* __restrict__ x,
                      const float* __restrict__ cb,
                      float* __restrict__ o_xhat,
                      float* __restrict__ o_idx,
                      float* __restrict__ o_sign,
                      float* __restrict__ o_norm)
{
    const int tid  = threadIdx.x;
    const int lane = tid & 31;
    const int warp = tid >> 5;          // 0..31
    const int quad = warp >> 2;         // 0..7 — independent mrow groups
    const int g    = lane >> 2;
    const int tig  = lane & 3;
    const int mrow = quad * 16;
    const int ncol = (warp & 3) * 32;

    const float c0 = cb[0], c1 = cb[1], c2 = cb[2], c3 = cb[3];
    const float b0 = 0.5f * (c0 + c1), b1 = 0.5f * (c1 + c2), b2 = 0.5f * (c2 + c3);
    const float scale = 1.2533141373155003f / 128.0f;

    // ---- resident P1, P2, PT1 ----
    {
        uint4* d1 = (uint4*)(smc + SM_P1);
        uint4* d2 = (uint4*)(smc + SM_P2);
        uint4* d3 = (uint4*)(smc + SM_PT1);
        const uint4* s1 = (const uint4*)gP1;
        const uint4* s2 = (const uint4*)gP2;
        const uint4* s3 = (const uint4*)gPT1;
        for (int i = tid; i < TILE_B / 16; i += NTHREADS){
            d1[i] = s1[i]; d2[i] = s2[i]; d3[i] = s3[i];
        }
    }

    const uint32_t aLane = (uint32_t)((mrow + (lane & 15)) * ROWB + (lane >> 4) * 16);
    const uint32_t bLane = (uint32_t)((ncol + (lane & 7) + 8 * (lane >> 4)) * ROWB + ((lane >> 3) & 1) * 16);
    const uint32_t sP1 = su(smc + SM_P1) + bLane;
    const uint32_t sP2 = su(smc + SM_P2) + bLane;
    const uint32_t sPT = su(smc + SM_PT1) + bLane;
    const uint32_t sR1 = su(smc + SM_R1) + aLane;
    const uint32_t sR2 = su(smc + SM_R2) + aLane;
    const uint32_t sSG = su(smc + SM_SGN) + aLane;

    // quad-local token/elem mapping for the coalesced o_sign copy
    const int ctok = ((tid >> 7) << 4) + ((tid & 127) >> 3);
    const int cq   = tid & 7;

    int tb = blockIdx.x;
    int ib = 0;
    phaseA(tb, ib, x, o_idx, o_norm, c0, c1, c2, c3, b0, b1, b2, tid);
    __syncthreads();   // P visibility (cross-quad) + R(tb) visibility

    float acc1[4][4], acc2[4][4];
    #pragma unroll
    for (int j = 0; j < 4; j++)
        #pragma unroll
        for (int k = 0; k < 4; k++) acc1[j][k] = 0.0f;
    gemm1_only(acc1, sR1, sR2, sP1, sP2);
    QBAR(quad);        // quad done reading R rows before its phaseA(tn) overwrites

    while (true){
        const int tok0 = tb * 128;

        // ---- signs(tb) from acc1 -> SGN smem only (branch-free) ----
        {
            const int r0 = mrow + g;
            #pragma unroll
            for (int nt = 0; nt < 4; nt++){
                const int cc = ncol + 8 * nt + 2 * tig;
                uint32_t u0 = __float_as_uint(acc1[nt][0]);
                uint32_t u1 = __float_as_uint(acc1[nt][1]);
                uint32_t u2 = __float_as_uint(acc1[nt][2]);
                uint32_t u3 = __float_as_uint(acc1[nt][3]);
                uint32_t h01 = (0x3C00u | ((u0 >> 16) & 0x8000u)) |
                               ((0x3C00u | ((u1 >> 16) & 0x8000u)) << 16);
                uint32_t h23 = (0x3C00u | ((u2 >> 16) & 0x8000u)) |
                               ((0x3C00u | ((u3 >> 16) & 0x8000u)) << 16);
                *(uint32_t*)(smc + SM_SGN + (r0 * PITCH + cc) * 2)       = h01;
                *(uint32_t*)(smc + SM_SGN + ((r0 + 8) * PITCH + cc) * 2) = h23;
            }
        }

        const int tn = tb + GRID;
        const bool have = (tn < NTILES);
        const int in = ib ^ 1;
        if (have)
            phaseA(tn, in, x, o_idx, o_norm, c0, c1, c2, c3, b0, b1, b2, tid);
        QBAR(quad);        // SGN(tb) rows + R(tn) rows visible within quad

        // ---- coalesced o_sign copy from SGN (quad-local rows; stores drain under MMAs) ----
        if (o_sign){
            const char* sp = smc + SM_SGN + (ctok * PITCH + cq * 16) * 2;
            float* op = o_sign + (size_t)(tok0 + ctok) * DIMV + cq * 16;
            #pragma unroll
            for (int h = 0; h < 2; h++){
                uint4 w = *(const uint4*)(sp + h * 16);
                uint32_t arr[4] = {w.x, w.y, w.z, w.w};
                float f[8];
                #pragma unroll
                for (int k2 = 0; k2 < 4; k2++){
                    float2 ff = __half22float2(*reinterpret_cast<__half2*>(&arr[k2]));
                    f[k2 * 2] = ff.x; f[k2 * 2 + 1] = ff.y;
                }
                *(float4*)(op + 8 * h)     = make_float4(f[0], f[1], f[2], f[3]);
                *(float4*)(op + 8 * h + 4) = make_float4(f[4], f[5], f[6], f[7]);
            }
        }

        // ---- fused GEMMs (+ L2 prefetch of x for tile after next) ----
        {
            int tnn = tb + 2 * GRID;
            if (tnn < NTILES){
                const float* pf = x + (size_t)tnn * (128 * DIMV) + (size_t)((tid * 16) & 16383);
                asm volatile("prefetch.global.L2 [%0];" :: "l"(pf));
            }
        }
        #pragma unroll
        for (int j = 0; j < 4; j++)
            #pragma unroll
            for (int k = 0; k < 4; k++){ acc1[j][k] = 0.0f; acc2[j][k] = 0.0f; }
        if (have) gemms_fused(acc1, acc2, sR1, sR2, sP1, sP2, sSG, sPT);
        else      gemm2_only(acc2, sSG, sPT);

        // ---- epilogue(tb): wide idx loads ----
        {
            const unsigned char* idxb = (const unsigned char*)(smc + SM_IDX + ib * 4096);
            const float* norms = (const float*)(smc + SM_NORM + ib * 512);
            const int r0 = mrow + g;
            const float cf0 = scale * norms[r0];
            const float cf1 = scale * norms[r0 + 8];
            const u64t wA = *(const u64t*)(idxb + r0 * 32 + (ncol >> 2));
            const u64t wB = *(const u64t*)(idxb + (r0 + 8) * 32 + (ncol >> 2));
            const int bsh = 8 * (tig >> 1) + 4 * (tig & 1);
            #pragma unroll
            for (int nt = 0; nt < 4; nt++){
                const int cc = ncol + 8 * nt + 2 * tig;
                const int sh = 16 * nt + bsh;
                unsigned i00 = (unsigned)(wA >> sh) & 3u;
                unsigned i01 = (unsigned)(wA >> (sh + 2)) & 3u;
                unsigned i10 = (unsigned)(wB >> sh) & 3u;
                unsigned i11 = (unsigned)(wB >> (sh + 2)) & 3u;
                float m00 = (i00 == 0) ? c0 : (i00 == 1) ? c1 : (i00 == 2) ? c2 : c3;
                float m01 = (i01 == 0) ? c0 : (i01 == 1) ? c1 : (i01 == 2) ? c2 : c3;
                float m10 = (i10 == 0) ? c0 : (i10 == 1) ? c1 : (i10 == 2) ? c2 : c3;
                float m11 = (i11 == 0) ? c0 : (i11 == 1) ? c1 : (i11 == 2) ? c2 : c3;
                *(float2*)(o_xhat + (size_t)(tok0 + r0) * DIMV + cc) =
                    make_float2(fmaf(cf0, acc2[nt][0], m00), fmaf(cf0, acc2[nt][1], m01));
                *(float2*)(o_xhat + (size_t)(tok0 + r0 + 8) * DIMV + cc) =
                    make_float2(fmaf(cf1, acc2[nt][2], m10), fmaf(cf1, acc2[nt][3], m11));
            }
        }

        if (!have) break;
        QBAR(quad);        // quad's fused reads of SGN/R done before next overwrite
        tb = tn;
        ib = in;
    }
}

extern "C" void kernel_launch(void* const* d_in, const int* in_sizes, int n_in,
                              void* d_out, int out_size)
{
    const float* x    = (const float*)d_in[0];
    const float* cb   = (const float*)d_in[1];
    const float* proj = (const float*)d_in[2];

    float* o_x = (float*)d_out;
    float* o_i = nullptr;
    float* o_s = nullptr;
    float* o_n = nullptr;
    long long need = 3LL * NELEM_LL + (long long)NTOK;
    if ((long long)out_size >= need){
        o_i = o_x + NELEM_LL;
        o_s = o_x + 2 * NELEM_LL;
        o_n = o_x + 3 * NELEM_LL;
    }

    prep_kernel<<<64, 256>>>(proj);
    cudaFuncSetAttribute(turboquant_mma_kernel,
                         cudaFuncAttributeMaxDynamicSharedMemorySize, SM_TOTAL);
    turboquant_mma_kernel<<<GRID, NTHREADS, SM_TOTAL>>>(x, cb, o_x, o_i, o_s, o_n);
}

// round 17
// speedup vs baseline: 1.3101x; 1.3101x over previous
#include <cuda_runtime.h>
#include <cuda_fp16.h>
#include <stdint.h>

#define DIMV 128
#define NTOK (2*32*8192)
#define NELEM_LL (524288LL * 128LL)
#define NTHREADS 1024
#define NTILES 4096
#define GRID 152
#define PITCH 136
#define ROWB (PITCH * 2)             // 272
#define TILE_B (128 * ROWB)          // 34816

// smem byte offsets
#define SM_P1   0
#define SM_P2   34816
#define SM_PT1  69632
#define SM_R1   104448
#define SM_R2   139264
#define SM_SGN  174080
#define SM_IDX  208896               // 2 buffers x 4096 B
#define SM_NORM 217088               // 2 buffers x 512 B
#define SM_TOTAL 218112

typedef unsigned long long u64t;

__device__ __align__(16) __half gP1[128 * PITCH];
__device__ __align__(16) __half gP2[128 * PITCH];
__device__ __align__(16) __half gPT1[128 * PITCH];

__device__ __forceinline__ uint32_t hpack(__half a, __half b){
    __half2 t = __halves2half2(a, b);
    return *reinterpret_cast<uint32_t*>(&t);
}
__device__ __forceinline__ uint32_t su(const void* p){
    uint32_t a;
    asm("{ .reg .u64 t; cvta.to.shared.u64 t, %1; cvt.u32.u64 %0, t; }" : "=r"(a) : "l"(p));
    return a;
}

__global__ void prep_kernel(const float* __restrict__ proj){
    int i = blockIdx.x * blockDim.x + threadIdx.x;
    int e = i >> 7, d = i & 127;
    float v = proj[i];
    __half h1 = __float2half_rn(v);
    __half h2 = __float2half_rn(v - __half2float(h1));
    gP1[e * PITCH + d] = h1;
    gP2[e * PITCH + d] = h2;
    gPT1[d * PITCH + e] = h1;
}

extern __shared__ char smc[];

#define LDSM4(r0_, r1_, r2_, r3_, addr_) \
    asm volatile("ldmatrix.sync.aligned.m8n8.x4.shared.b16 {%0,%1,%2,%3}, [%4];" \
        : "=r"(r0_), "=r"(r1_), "=r"(r2_), "=r"(r3_) : "r"(addr_))

#define MMA16816(acc_, a_, b0_, b1_) \
    asm volatile("mma.sync.aligned.m16n8k16.row.col.f32.f16.f16.f32 " \
        "{%0,%1,%2,%3}, {%4,%5,%6,%7}, {%8,%9}, {%0,%1,%2,%3};" \
        : "+f"((acc_)[0]), "+f"((acc_)[1]), "+f"((acc_)[2]), "+f"((acc_)[3]) \
        : "r"((a_)[0]), "r"((a_)[1]), "r"((a_)[2]), "r"((a_)[3]), "r"(b0_), "r"(b1_))

// quad barrier: 4 warps (128 threads) sharing one mrow group
#define QBAR(id_) asm volatile("bar.sync %0, 128;" :: "r"(id_) : "memory")

// GEMM1 only (prologue): acc1 += r1*P1 + r2*P1 + r1*P2   (warp tile 16x32)
__device__ __forceinline__ void gemm1_only(float acc[4][4],
                                           uint32_t aR1, uint32_t aR2,
                                           uint32_t bP1, uint32_t bP2){
    #pragma unroll
    for (int kt = 0; kt < 8; kt++){
        uint32_t A1[4], A2[4];
        LDSM4(A1[0], A1[1], A1[2], A1[3], aR1 + kt * 32);
        LDSM4(A2[0], A2[1], A2[2], A2[3], aR2 + kt * 32);
        {
            uint32_t B[4][2];
            #pragma unroll
            for (int np = 0; np < 2; np++)
                LDSM4(B[2*np][0], B[2*np][1], B[2*np+1][0], B[2*np+1][1], bP1 + np * (16 * ROWB) + kt * 32);
            #pragma unroll
            for (int nt = 0; nt < 4; nt++){
                MMA16816(acc[nt], A1, B[nt][0], B[nt][1]);
                MMA16816(acc[nt], A2, B[nt][0], B[nt][1]);
            }
        }
        {
            uint32_t B[4][2];
            #pragma unroll
            for (int np = 0; np < 2; np++)
                LDSM4(B[2*np][0], B[2*np][1], B[2*np+1][0], B[2*np+1][1], bP2 + np * (16 * ROWB) + kt * 32);
            #pragma unroll
            for (int nt = 0; nt < 4; nt++)
                MMA16816(acc[nt], A1, B[nt][0], B[nt][1]);
        }
    }
}

// fused: acc1 = GEMM1(next tile), acc2 = GEMM2(cur tile, signs * PT1)
__device__ __forceinline__ void gemms_fused(float acc1[4][4], float acc2[4][4],
                                            uint32_t aR1, uint32_t aR2,
                                            uint32_t bP1, uint32_t bP2,
                                            uint32_t aSG, uint32_t bPT){
    #pragma unroll
    for (int kt = 0; kt < 8; kt++){
        uint32_t A1[4], A2[4];
        LDSM4(A1[0], A1[1], A1[2], A1[3], aR1 + kt * 32);
        LDSM4(A2[0], A2[1], A2[2], A2[3], aR2 + kt * 32);
        {
            uint32_t B[4][2];
            #pragma unroll
            for (int np = 0; np < 2; np++)
                LDSM4(B[2*np][0], B[2*np][1], B[2*np+1][0], B[2*np+1][1], bP1 + np * (16 * ROWB) + kt * 32);
            #pragma unroll
            for (int nt = 0; nt < 4; nt++){
                MMA16816(acc1[nt], A1, B[nt][0], B[nt][1]);
                MMA16816(acc1[nt], A2, B[nt][0], B[nt][1]);
            }
        }
        {
            uint32_t B[4][2];
            #pragma unroll
            for (int np = 0; np < 2; np++)
                LDSM4(B[2*np][0], B[2*np][1], B[2*np+1][0], B[2*np+1][1], bP2 + np * (16 * ROWB) + kt * 32);
            #pragma unroll
            for (int nt = 0; nt < 4; nt++)
                MMA16816(acc1[nt], A1, B[nt][0], B[nt][1]);
        }
        {
            uint32_t S[4], T[4][2];
            LDSM4(S[0], S[1], S[2], S[3], aSG + kt * 32);
            #pragma unroll
            for (int np = 0; np < 2; np++)
                LDSM4(T[2*np][0], T[2*np][1], T[2*np+1][0], T[2*np+1][1], bPT + np * (16 * ROWB) + kt * 32);
            #pragma unroll
            for (int nt = 0; nt < 4; nt++)
                MMA16816(acc2[nt], S, T[nt][0], T[nt][1]);
        }
    }
}

// GEMM2 only (final tile)
__device__ __forceinline__ void gemm2_only(float acc[4][4], uint32_t aSG, uint32_t bPT){
    #pragma unroll
    for (int kt = 0; kt < 8; kt++){
        uint32_t S[4], T[4][2];
        LDSM4(S[0], S[1], S[2], S[3], aSG + kt * 32);
        #pragma unroll
        for (int np = 0; np < 2; np++)
            LDSM4(T[2*np][0], T[2*np][1], T[2*np+1][0], T[2*np+1][1], bPT + np * (16 * ROWB) + kt * 32);
        #pragma unroll
        for (int nt = 0; nt < 4; nt++)
            MMA16816(acc[nt], S, T[nt][0], T[nt][1]);
    }
}

// phaseA, quad-local tokens; coalesced element ownership: thread covers
// elems e = 4q + 32j (j=0..3), so each warp j-iteration touches dense 128B lines.
__device__ __forceinline__ void phaseA(int tile, int p, const float* __restrict__ x,
                                       float* __restrict__ o_idx, float* __restrict__ o_norm,
                                       float c0, float c1, float c2, float c3,
                                       float b0, float b1, float b2, int tid){
    const int tok = ((tid >> 7) << 4) + ((tid & 127) >> 3);
    const int q = tid & 7;
    const int tok0 = tile * 128;
    const float* xr = x + (size_t)(tok0 + tok) * DIMV + 4 * q;
    char* r1t = smc + SM_R1 + (tok * PITCH + 4 * q) * 2;
    char* r2t = smc + SM_R2 + (tok * PITCH + 4 * q) * 2;
    unsigned char* idxb = (unsigned char*)(smc + SM_IDX + p * 4096);
    float* norms = (float*)(smc + SM_NORM + p * 512);

    float ssq = 0.0f;
    #pragma unroll
    for (int j = 0; j < 4; j++){
        float4 xv = *(const float4*)(xr + 32 * j);
        float vf[4] = {xv.x, xv.y, xv.z, xv.w};
        __half h1[4], h2[4];
        float iv[4];
        uint32_t bits = 0;
        #pragma unroll
        for (int qq = 0; qq < 4; qq++){
            float v = vf[qq];
            int ix = (v > b0) + (v > b1) + (v > b2);
            float m = (ix == 0) ? c0 : (ix == 1) ? c1 : (ix == 2) ? c2 : c3;
            float r = v - m;
            ssq += r * r;
            iv[qq] = (float)ix;
            bits |= ((uint32_t)ix) << (qq * 2);
            h1[qq] = __float2half_rn(r);
            h2[qq] = __float2half_rn(r - __half2float(h1[qq]));
        }
        uint2 w1, w2;
        w1.x = hpack(h1[0], h1[1]); w1.y = hpack(h1[2], h1[3]);
        w2.x = hpack(h2[0], h2[1]); w2.y = hpack(h2[2], h2[3]);
        *(uint2*)(r1t + 64 * j) = w1;
        *(uint2*)(r2t + 64 * j) = w2;
        idxb[tok * 32 + q + 8 * j] = (unsigned char)bits;
        if (o_idx)
            *(float4*)(o_idx + (size_t)(tok0 + tok) * DIMV + 4 * q + 32 * j) =
                make_float4(iv[0], iv[1], iv[2], iv[3]);
    }
    ssq += __shfl_xor_sync(0xffffffffu, ssq, 1);
    ssq += __shfl_xor_sync(0xffffffffu, ssq, 2);
    ssq += __shfl_xor_sync(0xffffffffu, ssq, 4);
    if (q == 0){
        float nv = sqrtf(ssq);
        norms[tok] = nv;
        if (o_norm) o_norm[tok0 + tok] = nv;
    }
}

__global__ void __launch_bounds__(NTHREADS, 1)
turboquant_mma_kernel(const float* __restrict__ x,
                      const float* __restrict__ cb,
                      float* __restrict__ o_xhat,
                      float* __restrict__ o_idx,
                      float* __restrict__ o_sign,
                      float* __restrict__ o_norm)
{
    const int tid  = threadIdx.x;
    const int lane = tid & 31;
    const int warp = tid >> 5;          // 0..31
    const int quad = warp >> 2;         // 0..7 — independent mrow groups
    const int g    = lane >> 2;
    const int tig  = lane & 3;
    const int mrow = quad * 16;
    const int ncol = (warp & 3) * 32;

    const float c0 = cb[0], c1 = cb[1], c2 = cb[2], c3 = cb[3];
    const float b0 = 0.5f * (c0 + c1), b1 = 0.5f * (c1 + c2), b2 = 0.5f * (c2 + c3);
    const float scale = 1.2533141373155003f / 128.0f;

    // ---- resident P1, P2, PT1 ----
    {
        uint4* d1 = (uint4*)(smc + SM_P1);
        uint4* d2 = (uint4*)(smc + SM_P2);
        uint4* d3 = (uint4*)(smc + SM_PT1);
        const uint4* s1 = (const uint4*)gP1;
        const uint4* s2 = (const uint4*)gP2;
        const uint4* s3 = (const uint4*)gPT1;
        for (int i = tid; i < TILE_B / 16; i += NTHREADS){
            d1[i] = s1[i]; d2[i] = s2[i]; d3[i] = s3[i];
        }
    }

    const uint32_t aLane = (uint32_t)((mrow + (lane & 15)) * ROWB + (lane >> 4) * 16);
    const uint32_t bLane = (uint32_t)((ncol + (lane & 7) + 8 * (lane >> 4)) * ROWB + ((lane >> 3) & 1) * 16);
    const uint32_t sP1 = su(smc + SM_P1) + bLane;
    const uint32_t sP2 = su(smc + SM_P2) + bLane;
    const uint32_t sPT = su(smc + SM_PT1) + bLane;
    const uint32_t sR1 = su(smc + SM_R1) + aLane;
    const uint32_t sR2 = su(smc + SM_R2) + aLane;
    const uint32_t sSG = su(smc + SM_SGN) + aLane;

    int tb = blockIdx.x;
    int ib = 0;
    phaseA(tb, ib, x, o_idx, o_norm, c0, c1, c2, c3, b0, b1, b2, tid);
    __syncthreads();   // P visibility (cross-quad) + R(tb) visibility

    float acc1[4][4], acc2[4][4];
    #pragma unroll
    for (int j = 0; j < 4; j++)
        #pragma unroll
        for (int k = 0; k < 4; k++) acc1[j][k] = 0.0f;
    gemm1_only(acc1, sR1, sR2, sP1, sP2);
    QBAR(quad);        // quad done reading R rows before its phaseA(tn) overwrites

    while (true){
        const int tok0 = tb * 128;

        // ---- signs(tb) from acc1 -> SGN + o_sign (branch-free, fragment layout) ----
        {
            const int r0 = mrow + g;
            #pragma unroll
            for (int nt = 0; nt < 4; nt++){
                const int cc = ncol + 8 * nt + 2 * tig;
                uint32_t u0 = __float_as_uint(acc1[nt][0]);
                uint32_t u1 = __float_as_uint(acc1[nt][1]);
                uint32_t u2 = __float_as_uint(acc1[nt][2]);
                uint32_t u3 = __float_as_uint(acc1[nt][3]);
                if (o_sign){
                    *(float2*)(o_sign + (size_t)(tok0 + r0) * DIMV + cc) =
                        make_float2(__uint_as_float(0x3F800000u | (u0 & 0x80000000u)),
                                    __uint_as_float(0x3F800000u | (u1 & 0x80000000u)));
                    *(float2*)(o_sign + (size_t)(tok0 + r0 + 8) * DIMV + cc) =
                        make_float2(__uint_as_float(0x3F800000u | (u2 & 0x80000000u)),
                                    __uint_as_float(0x3F800000u | (u3 & 0x80000000u)));
                }
                uint32_t h01 = (0x3C00u | ((u0 >> 16) & 0x8000u)) |
                               ((0x3C00u | ((u1 >> 16) & 0x8000u)) << 16);
                uint32_t h23 = (0x3C00u | ((u2 >> 16) & 0x8000u)) |
                               ((0x3C00u | ((u3 >> 16) & 0x8000u)) << 16);
                *(uint32_t*)(smc + SM_SGN + (r0 * PITCH + cc) * 2)       = h01;
                *(uint32_t*)(smc + SM_SGN + ((r0 + 8) * PITCH + cc) * 2) = h23;
            }
        }

        const int tn = tb + GRID;
        const bool have = (tn < NTILES);
        const int in = ib ^ 1;
        if (have)
            phaseA(tn, in, x, o_idx, o_norm, c0, c1, c2, c3, b0, b1, b2, tid);
        QBAR(quad);        // SGN(tb) rows + R(tn) rows visible within quad

        // ---- fused GEMMs (+ L2 prefetch of x for tile after next) ----
        {
            int tnn = tb + 2 * GRID;
            if (tnn < NTILES){
                const float* pf = x + (size_t)tnn * (128 * DIMV) + (size_t)((tid * 16) & 16383);
                asm volatile("prefetch.global.L2 [%0];" :: "l"(pf));
            }
        }
        #pragma unroll
        for (int j = 0; j < 4; j++)
            #pragma unroll
            for (int k = 0; k < 4; k++){ acc1[j][k] = 0.0f; acc2[j][k] = 0.0f; }
        if (have) gemms_fused(acc1, acc2, sR1, sR2, sP1, sP2, sSG, sPT);
        else      gemm2_only(acc2, sSG, sPT);

        // ---- epilogue(tb) ----
        {
            const unsigned char* idxb = (const unsigned char*)(smc + SM_IDX + ib * 4096);
            const float* norms = (const float*)(smc + SM_NORM + ib * 512);
            const int r0 = mrow + g;
            const float cf0 = scale * norms[r0];
            const float cf1 = scale * norms[r0 + 8];
            #pragma unroll
            for (int nt = 0; nt < 4; nt++){
                const int cc = ncol + 8 * nt + 2 * tig;
                const int sh = 2 * (cc & 3);
                unsigned bA = idxb[r0 * 32 + (cc >> 2)];
                unsigned bB = idxb[(r0 + 8) * 32 + (cc >> 2)];
                unsigned i00 = (bA >> sh) & 3u, i01 = (bA >> (sh + 2)) & 3u;
                unsigned i10 = (bB >> sh) & 3u, i11 = (bB >> (sh + 2)) & 3u;
                float m00 = (i00 == 0) ? c0 : (i00 == 1) ? c1 : (i00 == 2) ? c2 : c3;
                float m01 = (i01 == 0) ? c0 : (i01 == 1) ? c1 : (i01 == 2) ? c2 : c3;
                float m10 = (i10 == 0) ? c0 : (i10 == 1) ? c1 : (i10 == 2) ? c2 : c3;
                float m11 = (i11 == 0) ? c0 : (i11 == 1) ? c1 : (i11 == 2) ? c2 : c3;
                *(float2*)(o_xhat + (size_t)(tok0 + r0) * DIMV + cc) =
                    make_float2(fmaf(cf0, acc2[nt][0], m00), fmaf(cf0, acc2[nt][1], m01));
                *(float2*)(o_xhat + (size_t)(tok0 + r0 + 8) * DIMV + cc) =
                    make_float2(fmaf(cf1, acc2[nt][2], m10), fmaf(cf1, acc2[nt][3], m11));
            }
        }

        if (!have) break;
        QBAR(quad);        // quad's fused reads of SGN/R done before next overwrite
        tb = tn;
        ib = in;
    }
}

extern "C" void kernel_launch(void* const* d_in, const int* in_sizes, int n_in,
                              void* d_out, int out_size)
{
    const float* x    = (const float*)d_in[0];
    const float* cb   = (const float*)d_in[1];
    const float* proj = (const float*)d_in[2];

    float* o_x = (float*)d_out;
    float* o_i = nullptr;
    float* o_s = nullptr;
    float* o_n = nullptr;
    long long need = 3LL * NELEM_LL + (long long)NTOK;
    if ((long long)out_size >= need){
        o_i = o_x + NELEM_LL;
        o_s = o_x + 2 * NELEM_LL;
        o_n = o_x + 3 * NELEM_LL;
    }

    prep_kernel<<<64, 256>>>(proj);
    cudaFuncSetAttribute(turboquant_mma_kernel,
                         cudaFuncAttributeMaxDynamicSharedMemorySize, SM_TOTAL);
    turboquant_mma_kernel<<<GRID, NTHREADS, SM_TOTAL>>>(x, cb, o_x, o_i, o_s, o_n);
}